// round 14
// baseline (speedup 1.0000x reference)
#include <cuda_runtime.h>
#include <cuda_bf16.h>
#include <cstdint>
#include <math.h>

// Problem dims (fixed by the dataset)
#define B_ROWS 65536
#define D_IN   784
#define H_DIM  512
#define D_OUT  10
#define KCODE  512
#define BN_EPS 1e-5f

// ---------------- scratch (static device globals; no allocations) ----------------
__device__ __nv_bfloat16 g_b1hi[H_DIM * D_IN];           // split qW1
__device__ __nv_bfloat16 g_b1lo[H_DIM * D_IN];
__device__ float g_qW2[H_DIM * H_DIM];                   // fp32 qW2 (pre-fold)
__device__ __nv_bfloat16 g_b2hi[H_DIM * H_DIM];          // split (qW2 * s)
__device__ __nv_bfloat16 g_b2lo[H_DIM * H_DIM];
__device__ float g_b2f[H_DIM];                           // b2 + qW2 @ t
__device__ __nv_bfloat16 g_ahi[(size_t)B_ROWS * H_DIM];  // split h1 (hi)
__device__ __nv_bfloat16 g_alo[(size_t)B_ROWS * H_DIM];  // split h1 (lo)
__device__ float g_part[(size_t)8 * B_ROWS * D_OUT];     // out partials
__device__ float g_colsum[H_DIM];
__device__ float g_colsumsq[H_DIM];
__device__ float g_s[H_DIM];
__device__ float g_t[H_DIM];
__device__ float g_diff1;
__device__ float g_diff2;

// ---------------- zero accumulators ----------------
__global__ void zero_accums() {
    int t = threadIdx.x;
    if (t < H_DIM) { g_colsum[t] = 0.f; g_colsumsq[t] = 0.f; }
    if (t == 0) { g_diff1 = 0.f; g_diff2 = 0.f; }
}

// Reference-replicating fp32 helpers (no contraction allowed)
__device__ __forceinline__ float sq_sum_seq(const float* v, int n) {
    float s = __fmul_rn(v[0], v[0]);
    for (int d = 1; d < n; d++) s = __fadd_rn(s, __fmul_rn(v[d], v[d]));
    return s;
}
__device__ __forceinline__ void split_bf16(float x, __nv_bfloat16& h, __nv_bfloat16& l) {
    h = __float2bfloat16_rn(x);
    l = __float2bfloat16_rn(__fsub_rn(x, __bfloat162float(h)));
}
__device__ __forceinline__ uint32_t pack2(__nv_bfloat16 a, __nv_bfloat16 b) {
    __nv_bfloat162 h2 = __halves2bfloat162(a, b);
    return *(uint32_t*)&h2;
}

// ---------------- merged VQ quantize (argmin logic unchanged from passing R3) ----------------
// blocks [0, 448): W1 path;  blocks [448, 960): W2 path (stores fp32 qW2)
__global__ void quant_all(const float* __restrict__ W1, const float* __restrict__ E1,
                          const float* __restrict__ W2, const float* __restrict__ E2) {
    extern __shared__ float smemq[];
    if (blockIdx.x < 448) {
        float* sE  = smemq;
        float* sSe = smemq + KCODE * 28;

        for (int i = threadIdx.x; i < KCODE * 28; i += 128) {
            int k = i / 28, d = i % 28;
            sE[k * 28 + d] = E1[d * KCODE + k];
        }
        __syncthreads();
        for (int k = threadIdx.x; k < KCODE; k += 128)
            sSe[k] = sq_sum_seq(sE + k * 28, 28);
        __syncthreads();

        int gid = blockIdx.x * 128 + threadIdx.x;
        int blk = gid >> 2;
        int sub = gid & 3;
        int og = blk / 112;
        int ig = blk - og * 112;

        float v[28];
#pragma unroll
        for (int im = 0; im < 7; im++)
#pragma unroll
            for (int om = 0; om < 4; om++)
                v[im * 4 + om] = W1[(og * 4 + om) * D_IN + ig * 7 + im];
        float Sv = sq_sum_seq(v, 28);

        float best = 3.402823e38f;
        int bi = 0x7fffffff;
        for (int i = 0; i < 128; i++) {
            int k = (i << 2) | sub;
            const float* e = sE + k * 28;
            float dot = 0.f;
#pragma unroll
            for (int d = 0; d < 28; d++) dot = __fmaf_rn(v[d], e[d], dot);
            float dist = __fadd_rn(__fsub_rn(Sv, __fmul_rn(2.0f, dot)), sSe[k]);
            if (dist < best) { best = dist; bi = k; }
        }
#pragma unroll
        for (int off = 2; off >= 1; off >>= 1) {
            float ob = __shfl_down_sync(0xffffffffu, best, off);
            int   oi = __shfl_down_sync(0xffffffffu, bi, off);
            if (ob < best || (ob == best && oi < bi)) { best = ob; bi = oi; }
        }
        if (sub == 0) {
            const float* e = sE + bi * 28;
            float dsum = 0.f;
#pragma unroll
            for (int im = 0; im < 7; im++)
#pragma unroll
                for (int om = 0; om < 4; om++) {
                    int d = im * 4 + om;
                    float q = e[d];
                    int idx = (og * 4 + om) * D_IN + ig * 7 + im;
                    __nv_bfloat16 h, l;
                    split_bf16(q, h, l);
                    g_b1hi[idx] = h; g_b1lo[idx] = l;
                    float df = q - v[d];
                    dsum = fmaf(df, df, dsum);
                }
            atomicAdd(&g_diff1, dsum);
        }
    } else {
        float* sE  = smemq;                    // [KCODE][17]
        float* sSe = smemq + KCODE * 17;

        for (int i = threadIdx.x; i < KCODE * 16; i += 128) {
            int k = i >> 4, d = i & 15;
            sE[k * 17 + d] = E2[d * KCODE + k];
        }
        __syncthreads();
        for (int k = threadIdx.x; k < KCODE; k += 128) {
            const float* e = sE + k * 17;
            float s = __fmul_rn(e[0], e[0]);
            for (int d = 1; d < 16; d++) s = __fadd_rn(s, __fmul_rn(e[d], e[d]));
            sSe[k] = s;
        }
        __syncthreads();

        int gid = (blockIdx.x - 448) * 128 + threadIdx.x;
        int blk = gid >> 2;
        int sub = gid & 3;
        int og = blk >> 5;
        int ig = blk & 31;

        float v[16];
        const float4* wp = (const float4*)(W2 + og * H_DIM + ig * 16);
#pragma unroll
        for (int q4 = 0; q4 < 4; q4++) {
            float4 w = wp[q4];
            v[q4 * 4 + 0] = w.x; v[q4 * 4 + 1] = w.y; v[q4 * 4 + 2] = w.z; v[q4 * 4 + 3] = w.w;
        }
        float Sv = sq_sum_seq(v, 16);

        float best = 3.402823e38f;
        int bi = 0x7fffffff;
        for (int i = 0; i < 128; i++) {
            int k = (i << 2) | sub;
            const float* e = sE + k * 17;
            float dot = 0.f;
#pragma unroll
            for (int d = 0; d < 16; d++) dot = __fmaf_rn(v[d], e[d], dot);
            float dist = __fadd_rn(__fsub_rn(Sv, __fmul_rn(2.0f, dot)), sSe[k]);
            if (dist < best) { best = dist; bi = k; }
        }
#pragma unroll
        for (int off = 2; off >= 1; off >>= 1) {
            float ob = __shfl_down_sync(0xffffffffu, best, off);
            int   oi = __shfl_down_sync(0xffffffffu, bi, off);
            if (ob < best || (ob == best && oi < bi)) { best = ob; bi = oi; }
        }
        if (sub == 0) {
            const float* e = sE + bi * 17;
            float dsum = 0.f;
#pragma unroll
            for (int d = 0; d < 16; d++) {
                float q = e[d];
                g_qW2[og * H_DIM + ig * 16 + d] = q;
                float df = q - v[d];
                dsum = fmaf(df, df, dsum);
            }
            atomicAdd(&g_diff2, dsum);
        }
    }
}

// ---------------- common GEMM plumbing ----------------
#define TILE_SZ 6144                  // 128 rows * 48B
__device__ __forceinline__ uint32_t smem_u32(const void* p) {
    uint32_t a;
    asm("{ .reg .u64 t; cvta.to.shared.u64 t, %1; cvt.u32.u64 %0, t; }" : "=r"(a) : "l"(p));
    return a;
}
__device__ __forceinline__ void cp_async16_cg(uint32_t dst, const void* src) {
    asm volatile("cp.async.cg.shared.global [%0], [%1], 16;" :: "r"(dst), "l"(src));
}
#define CP_COMMIT() asm volatile("cp.async.commit_group;" ::: "memory")
#define CP_WAIT2()  asm volatile("cp.async.wait_group 2;" ::: "memory")
__device__ __forceinline__ void ldsm_x4(uint32_t* r, uint32_t addr) {
    asm volatile("ldmatrix.sync.aligned.m8n8.x4.shared.b16 {%0,%1,%2,%3}, [%4];"
                 : "=r"(r[0]), "=r"(r[1]), "=r"(r[2]), "=r"(r[3]) : "r"(addr));
}
__device__ __forceinline__ void mma_bf16(float* d, const uint32_t* a, const uint32_t* b) {
    asm volatile(
        "mma.sync.aligned.m16n8k16.row.col.f32.bf16.bf16.f32 "
        "{%0,%1,%2,%3}, {%4,%5,%6,%7}, {%8,%9}, {%0,%1,%2,%3};"
        : "+f"(d[0]), "+f"(d[1]), "+f"(d[2]), "+f"(d[3])
        : "r"(a[0]), "r"(a[1]), "r"(a[2]), "r"(a[3]), "r"(b[0]), "r"(b[1]));
}

// ---------------- GEMM1: A fp32 (in-kernel split), B pre-split; epilogue -> bf16 h1 + colstats ----------------
#define SM_A1   0                     // 2 bufs x (hi,lo)
#define SM_B1   (2 * 2 * TILE_SZ)     // 24576; 4 stages x (hi,lo)
#define G1SMEM  (SM_B1 + 4 * 2 * TILE_SZ)   // 73728

__global__ __launch_bounds__(256, 2) void mma_gemm1(
    const float* __restrict__ A,
    const __nv_bfloat16* __restrict__ Bhi, const __nv_bfloat16* __restrict__ Blo,
    const float* __restrict__ bias,
    __nv_bfloat16* __restrict__ Chi, __nv_bfloat16* __restrict__ Clo, int K)
{
    extern __shared__ char sm[];
    char* smA = sm + SM_A1;
    const uint32_t smA_u = smem_u32(sm) + SM_A1;
    const uint32_t smB_u = smem_u32(sm) + SM_B1;

    const int tid = threadIdx.x;
    const int wid = tid >> 5, lane = tid & 31;
    const int bm = blockIdx.y * 128;
    const int bn = blockIdx.x * 128;

    const int row = tid >> 1;
    const int colbase = (tid & 1) * 8;
    const float* Ap = A + (size_t)(bm + row) * K + colbase;
    const __nv_bfloat16* bph = Bhi + (size_t)(bn + row) * K + colbase;
    const __nv_bfloat16* bpl = Blo + (size_t)(bn + row) * K + colbase;
    const uint32_t dsto = (uint32_t)(row * 48 + colbase * 2);

    const int nkt = K / 16;

    auto issue_B = [&](int kt, int stage) {
        uint32_t base = smB_u + stage * (2 * TILE_SZ) + dsto;
        const size_t ko = (size_t)kt * 16;
        cp_async16_cg(base, bph + ko);
        cp_async16_cg(base + TILE_SZ, bpl + ko);
    };

    float4 stA0, stA1;
    auto store_A = [&](int buf) {
        float a[8] = {stA0.x, stA0.y, stA0.z, stA0.w, stA1.x, stA1.y, stA1.z, stA1.w};
        float ah[8], al[8];
#pragma unroll
        for (int j = 0; j < 8; j++) {
            float fh = __bfloat162float(__float2bfloat16_rn(a[j]));
            ah[j] = fh; al[j] = __fsub_rn(a[j], fh);
        }
        char* dst = smA + buf * (2 * TILE_SZ) + dsto;
        *(uint4*)dst = make_uint4(pack2(__float2bfloat16_rn(ah[0]), __float2bfloat16_rn(ah[1])),
                                  pack2(__float2bfloat16_rn(ah[2]), __float2bfloat16_rn(ah[3])),
                                  pack2(__float2bfloat16_rn(ah[4]), __float2bfloat16_rn(ah[5])),
                                  pack2(__float2bfloat16_rn(ah[6]), __float2bfloat16_rn(ah[7])));
        *(uint4*)(dst + TILE_SZ) = make_uint4(pack2(__float2bfloat16_rn(al[0]), __float2bfloat16_rn(al[1])),
                                              pack2(__float2bfloat16_rn(al[2]), __float2bfloat16_rn(al[3])),
                                              pack2(__float2bfloat16_rn(al[4]), __float2bfloat16_rn(al[5])),
                                              pack2(__float2bfloat16_rn(al[6]), __float2bfloat16_rn(al[7])));
    };

    float acc[2][8][4];
#pragma unroll
    for (int mt = 0; mt < 2; mt++)
#pragma unroll
        for (int nt = 0; nt < 8; nt++)
#pragma unroll
            for (int j = 0; j < 4; j++) acc[mt][nt][j] = 0.f;

    const int m0w = (wid & 3) * 32;
    const int n0w = (wid >> 2) * 64;
    const int frow = lane >> 2;
    const int fk2 = (lane & 3) * 2;

    const uint32_t arow = (uint32_t)((lane & 7) + ((lane >> 3) & 1) * 8);
    const uint32_t aseg = (uint32_t)(((lane >> 4) & 1) * 16);
    const uint32_t brow = (uint32_t)(((lane >> 4) & 1) * 8 + (lane & 7));
    const uint32_t bseg = (uint32_t)(((lane >> 3) & 1) * 16);

    // prologue
    stA0 = *(const float4*)Ap;  stA1 = *(const float4*)(Ap + 4);
    store_A(0);
    issue_B(0, 0); CP_COMMIT();
    issue_B(1, 1); CP_COMMIT();
    issue_B(2, 2); CP_COMMIT();
    if (nkt > 1) {
        stA0 = *(const float4*)(Ap + 16);  stA1 = *(const float4*)(Ap + 20);
    }

    for (int kt = 0; kt < nkt; kt++) {
        CP_WAIT2();
        __syncthreads();
        if (kt + 3 < nkt) issue_B(kt + 3, (kt + 3) & 3);
        CP_COMMIT();

        const uint32_t tAhi = smA_u + (kt & 1) * (2 * TILE_SZ);
        const uint32_t tAlo = tAhi + TILE_SZ;
        const uint32_t tBhi = smB_u + (kt & 3) * (2 * TILE_SZ);
        const uint32_t tBlo = tBhi + TILE_SZ;

        uint32_t ah[2][4], al[2][4];
#pragma unroll
        for (int mt = 0; mt < 2; mt++) {
            uint32_t ao = (uint32_t)((m0w + mt * 16 + arow) * 48) + aseg;
            ldsm_x4(ah[mt], tAhi + ao);
            ldsm_x4(al[mt], tAlo + ao);
        }
#pragma unroll
        for (int ntp = 0; ntp < 4; ntp++) {
            uint32_t bo = (uint32_t)((n0w + ntp * 16 + brow) * 48) + bseg;
            uint32_t bh[4], bl[4];
            ldsm_x4(bh, tBhi + bo);
            ldsm_x4(bl, tBlo + bo);
#pragma unroll
            for (int h = 0; h < 2; h++) {
                int nt = ntp * 2 + h;
#pragma unroll
                for (int mt = 0; mt < 2; mt++) {
                    mma_bf16(acc[mt][nt], ah[mt], bh + h * 2);
                    mma_bf16(acc[mt][nt], ah[mt], bl + h * 2);
                    mma_bf16(acc[mt][nt], al[mt], bh + h * 2);
                }
            }
        }
        if (kt + 1 < nkt) {
            store_A((kt + 1) & 1);
            if (kt + 2 < nkt) {
                const float* ap = Ap + (size_t)(kt + 2) * 16;
                stA0 = *(const float4*)ap;  stA1 = *(const float4*)(ap + 4);
            }
        }
    }

    // epilogue: bias + relu -> split bf16 h1 (hi/lo), fused column stats
    float cs[8][2], cs2[8][2];
#pragma unroll
    for (int nt = 0; nt < 8; nt++) { cs[nt][0] = cs[nt][1] = 0.f; cs2[nt][0] = cs2[nt][1] = 0.f; }
#pragma unroll
    for (int mt = 0; mt < 2; mt++) {
        int m = bm + m0w + mt * 16 + frow;
#pragma unroll
        for (int nt = 0; nt < 8; nt++) {
            int n = bn + n0w + nt * 8 + fk2;
            float bx = __ldg(&bias[n]), by = __ldg(&bias[n + 1]);
            float o0 = fmaxf(acc[mt][nt][0] + bx, 0.f);
            float o1 = fmaxf(acc[mt][nt][1] + by, 0.f);
            float o2 = fmaxf(acc[mt][nt][2] + bx, 0.f);
            float o3 = fmaxf(acc[mt][nt][3] + by, 0.f);
            __nv_bfloat16 h0, l0, h1, l1, h2, l2, h3, l3;
            split_bf16(o0, h0, l0); split_bf16(o1, h1, l1);
            split_bf16(o2, h2, l2); split_bf16(o3, h3, l3);
            size_t i0 = ((size_t)m * H_DIM + n) >> 1;          // uint32 index
            size_t i1 = ((size_t)(m + 8) * H_DIM + n) >> 1;
            ((uint32_t*)Chi)[i0] = pack2(h0, h1);
            ((uint32_t*)Clo)[i0] = pack2(l0, l1);
            ((uint32_t*)Chi)[i1] = pack2(h2, h3);
            ((uint32_t*)Clo)[i1] = pack2(l2, l3);
            cs[nt][0] += o0 + o2;   cs[nt][1] += o1 + o3;
            cs2[nt][0] = fmaf(o0, o0, fmaf(o2, o2, cs2[nt][0]));
            cs2[nt][1] = fmaf(o1, o1, fmaf(o3, o3, cs2[nt][1]));
        }
    }
#pragma unroll
    for (int off = 4; off <= 16; off <<= 1)
#pragma unroll
        for (int nt = 0; nt < 8; nt++)
#pragma unroll
            for (int j = 0; j < 2; j++) {
                cs[nt][j]  += __shfl_down_sync(0xffffffffu, cs[nt][j], off);
                cs2[nt][j] += __shfl_down_sync(0xffffffffu, cs2[nt][j], off);
            }
    if (lane < 4) {
#pragma unroll
        for (int nt = 0; nt < 8; nt++)
#pragma unroll
            for (int j = 0; j < 2; j++) {
                int n = bn + n0w + nt * 8 + lane * 2 + j;
                atomicAdd(&g_colsum[n], cs[nt][j]);
                atomicAdd(&g_colsumsq[n], cs2[nt][j]);
            }
    }
}

// ---------------- GEMM2: both operands pre-split bf16 streamed via cp.async ----------------
// partials of (A @ B^T + b2f) relu'd then @ W3^T  -> g_part
#define SM_A2   0                      // 4 stages x (hi,lo)
#define SM_B2   (4 * 2 * TILE_SZ)      // 49152
#define G2SMEM  (SM_B2 + 4 * 2 * TILE_SZ)   // 98304

__global__ __launch_bounds__(256, 2) void mma_gemm2(
    const __nv_bfloat16* __restrict__ Ahi, const __nv_bfloat16* __restrict__ Alo,
    const __nv_bfloat16* __restrict__ Bhi, const __nv_bfloat16* __restrict__ Blo,
    const float* __restrict__ bias, const float* __restrict__ W3g, int K)
{
    extern __shared__ char sm[];
    const uint32_t smA_u = smem_u32(sm) + SM_A2;
    const uint32_t smB_u = smem_u32(sm) + SM_B2;

    const int tid = threadIdx.x;
    const int wid = tid >> 5, lane = tid & 31;
    const int bm = blockIdx.y * 128;
    const int bn = blockIdx.x * 128;

    const int row = tid >> 1;
    const int colbase = (tid & 1) * 8;
    const __nv_bfloat16* aph = Ahi + (size_t)(bm + row) * K + colbase;
    const __nv_bfloat16* apl = Alo + (size_t)(bm + row) * K + colbase;
    const __nv_bfloat16* bph = Bhi + (size_t)(bn + row) * K + colbase;
    const __nv_bfloat16* bpl = Blo + (size_t)(bn + row) * K + colbase;
    const uint32_t dsto = (uint32_t)(row * 48 + colbase * 2);

    const int nkt = K / 16;

    auto issue_stage = [&](int kt, int stage) {
        const size_t ko = (size_t)kt * 16;
        uint32_t ab = smA_u + stage * (2 * TILE_SZ) + dsto;
        uint32_t bb = smB_u + stage * (2 * TILE_SZ) + dsto;
        cp_async16_cg(ab, aph + ko);
        cp_async16_cg(ab + TILE_SZ, apl + ko);
        cp_async16_cg(bb, bph + ko);
        cp_async16_cg(bb + TILE_SZ, bpl + ko);
    };

    float acc[2][8][4];
#pragma unroll
    for (int mt = 0; mt < 2; mt++)
#pragma unroll
        for (int nt = 0; nt < 8; nt++)
#pragma unroll
            for (int j = 0; j < 4; j++) acc[mt][nt][j] = 0.f;

    const int m0w = (wid & 3) * 32;
    const int n0w = (wid >> 2) * 64;
    const int frow = lane >> 2;
    const int fk2 = (lane & 3) * 2;

    const uint32_t arow = (uint32_t)((lane & 7) + ((lane >> 3) & 1) * 8);
    const uint32_t aseg = (uint32_t)(((lane >> 4) & 1) * 16);
    const uint32_t brow = (uint32_t)(((lane >> 4) & 1) * 8 + (lane & 7));
    const uint32_t bseg = (uint32_t)(((lane >> 3) & 1) * 16);

    issue_stage(0, 0); CP_COMMIT();
    issue_stage(1, 1); CP_COMMIT();
    issue_stage(2, 2); CP_COMMIT();

    for (int kt = 0; kt < nkt; kt++) {
        CP_WAIT2();
        __syncthreads();
        if (kt + 3 < nkt) issue_stage(kt + 3, (kt + 3) & 3);
        CP_COMMIT();

        const uint32_t tAhi = smA_u + (kt & 3) * (2 * TILE_SZ);
        const uint32_t tAlo = tAhi + TILE_SZ;
        const uint32_t tBhi = smB_u + (kt & 3) * (2 * TILE_SZ);
        const uint32_t tBlo = tBhi + TILE_SZ;

        uint32_t ah[2][4], al[2][4];
#pragma unroll
        for (int mt = 0; mt < 2; mt++) {
            uint32_t ao = (uint32_t)((m0w + mt * 16 + arow) * 48) + aseg;
            ldsm_x4(ah[mt], tAhi + ao);
            ldsm_x4(al[mt], tAlo + ao);
        }
#pragma unroll
        for (int ntp = 0; ntp < 4; ntp++) {
            uint32_t bo = (uint32_t)((n0w + ntp * 16 + brow) * 48) + bseg;
            uint32_t bh[4], bl[4];
            ldsm_x4(bh, tBhi + bo);
            ldsm_x4(bl, tBlo + bo);
#pragma unroll
            for (int h = 0; h < 2; h++) {
                int nt = ntp * 2 + h;
#pragma unroll
                for (int mt = 0; mt < 2; mt++) {
                    mma_bf16(acc[mt][nt], ah[mt], bh + h * 2);
                    mma_bf16(acc[mt][nt], ah[mt], bl + h * 2);
                    mma_bf16(acc[mt][nt], al[mt], bh + h * 2);
                }
            }
        }
    }

    // fused output layer: partials of relu(acc + b2f) @ W3^T into g_part (no atomics)
    __syncthreads();
    float* sW3 = (float*)sm;     // [10][128] W3 slice for this bn
    for (int idx = tid; idx < 10 * 128; idx += 256) {
        int j = idx >> 7, nl = idx & 127;
        sW3[idx] = W3g[j * H_DIM + bn + nl];
    }
    __syncthreads();
    const int half = wid >> 2;
    float* pslice = g_part + ((size_t)(blockIdx.x * 2 + half)) * ((size_t)B_ROWS * D_OUT);
#pragma unroll
    for (int mt = 0; mt < 2; mt++) {
        float p0[10], p1[10];
#pragma unroll
        for (int j = 0; j < 10; j++) { p0[j] = 0.f; p1[j] = 0.f; }
#pragma unroll
        for (int nt = 0; nt < 8; nt++) {
            int nl = n0w + nt * 8 + fk2;
            float bx = __ldg(&bias[bn + nl]), by = __ldg(&bias[bn + nl + 1]);
            float o0 = fmaxf(acc[mt][nt][0] + bx, 0.f);
            float o1 = fmaxf(acc[mt][nt][1] + by, 0.f);
            float o2 = fmaxf(acc[mt][nt][2] + bx, 0.f);
            float o3 = fmaxf(acc[mt][nt][3] + by, 0.f);
#pragma unroll
            for (int j = 0; j < 10; j++) {
                float w0 = sW3[j * 128 + nl], w1 = sW3[j * 128 + nl + 1];
                p0[j] = fmaf(o0, w0, fmaf(o1, w1, p0[j]));
                p1[j] = fmaf(o2, w0, fmaf(o3, w1, p1[j]));
            }
        }
#pragma unroll
        for (int j = 0; j < 10; j++) {
            p0[j] += __shfl_xor_sync(0xffffffffu, p0[j], 1);
            p0[j] += __shfl_xor_sync(0xffffffffu, p0[j], 2);
            p1[j] += __shfl_xor_sync(0xffffffffu, p1[j], 1);
            p1[j] += __shfl_xor_sync(0xffffffffu, p1[j], 2);
        }
        if ((lane & 3) == 0) {
            int m = bm + m0w + mt * 16 + frow;
#pragma unroll
            for (int j = 0; j < 10; j++) {
                pslice[(size_t)m * D_OUT + j] = p0[j];
                pslice[(size_t)(m + 8) * D_OUT + j] = p1[j];
            }
        }
    }
}

// ---------------- reduce partials -> out ----------------
__global__ void reduce_out(const float* __restrict__ b3, float* __restrict__ out) {
    int i = blockIdx.x * 256 + threadIdx.x;
    if (i < B_ROWS * D_OUT) {
        float s = __ldg(&b3[i % D_OUT]);
#pragma unroll
        for (int p = 0; p < 8; p++)
            s += g_part[(size_t)p * ((size_t)B_ROWS * D_OUT) + i];
        out[i] = s;
    }
}

// ---------------- BN scale/shift ----------------
__global__ void finalize_stats(const float* __restrict__ gamma, const float* __restrict__ beta) {
    int j = threadIdx.x;
    if (j < H_DIM) {
        float mu = g_colsum[j] * (1.f / (float)B_ROWS);
        float var = g_colsumsq[j] * (1.f / (float)B_ROWS) - mu * mu;
        float s = gamma[j] * (1.0f / sqrtf(var + BN_EPS));
        g_s[j] = s;
        g_t[j] = beta[j] - mu * s;
    }
}

// ---------------- fold BN into W2: W2f = qW2 * s (split bf16), b2f = b2 + qW2 @ t ----------------
__global__ void fold_w2(const float* __restrict__ b2) {
    int j = blockIdx.x;
    int t = threadIdx.x;
    __shared__ float red[128];
    float part = 0.f;
    for (int k = t; k < H_DIM; k += 128) {
        float w = g_qW2[j * H_DIM + k];
        float wf = __fmul_rn(w, g_s[k]);
        __nv_bfloat16 h, l;
        split_bf16(wf, h, l);
        g_b2hi[j * H_DIM + k] = h;
        g_b2lo[j * H_DIM + k] = l;
        part = fmaf(w, g_t[k], part);
    }
    red[t] = part;
    __syncthreads();
    for (int off = 64; off; off >>= 1) {
        if (t < off) red[t] += red[t + off];
        __syncthreads();
    }
    if (t == 0) g_b2f[j] = b2[j] + red[0];
}

// ---------------- diff scalar ----------------
__global__ void write_diff(float* __restrict__ out, int out_size) {
    if (out_size > B_ROWS * D_OUT)
        out[out_size - 1] = g_diff1 * (1.f / (float)(H_DIM * D_IN)) +
                            g_diff2 * (1.f / (float)(H_DIM * H_DIM));
}

// ---------------- launcher ----------------
extern "C" void kernel_launch(void* const* d_in, const int* in_sizes, int n_in,
                              void* d_out, int out_size) {
    const float* x      = (const float*)d_in[0];
    const float* W1     = (const float*)d_in[1];
    const float* b1     = (const float*)d_in[2];
    const float* gamma1 = (const float*)d_in[3];
    const float* beta1  = (const float*)d_in[4];
    const float* E1     = (const float*)d_in[5];
    const float* W2     = (const float*)d_in[6];
    const float* b2     = (const float*)d_in[7];
    const float* E2     = (const float*)d_in[8];
    const float* W3     = (const float*)d_in[9];
    const float* b3     = (const float*)d_in[10];
    float* out = (float*)d_out;

    (void)in_sizes; (void)n_in;

    cudaFuncSetAttribute(quant_all, cudaFuncAttributeMaxDynamicSharedMemorySize, 59392);
    cudaFuncSetAttribute(mma_gemm1, cudaFuncAttributeMaxDynamicSharedMemorySize, G1SMEM);
    cudaFuncSetAttribute(mma_gemm2, cudaFuncAttributeMaxDynamicSharedMemorySize, G2SMEM);

    __nv_bfloat16 *b1hip, *b1lop, *b2hip, *b2lop, *ahip, *alop;
    float *b2fp;
    cudaGetSymbolAddress((void**)&b1hip, g_b1hi);
    cudaGetSymbolAddress((void**)&b1lop, g_b1lo);
    cudaGetSymbolAddress((void**)&b2hip, g_b2hi);
    cudaGetSymbolAddress((void**)&b2lop, g_b2lo);
    cudaGetSymbolAddress((void**)&ahip, g_ahi);
    cudaGetSymbolAddress((void**)&alop, g_alo);
    cudaGetSymbolAddress((void**)&b2fp, g_b2f);

    zero_accums<<<1, 512>>>();
    quant_all<<<960, 128, 59392>>>(W1, E1, W2, E2);

    // h1 (bf16 hi/lo) = relu(x @ qW1^T + b1), fused colstats
    mma_gemm1<<<dim3(H_DIM / 128, B_ROWS / 128), 256, G1SMEM>>>(
        x, b1hip, b1lop, b1, ahip, alop, D_IN);

    finalize_stats<<<1, 512>>>(gamma1, beta1);
    fold_w2<<<512, 128>>>(b2);

    // partials of relu(h1 @ (qW2*s)^T + b2f) @ W3^T  (== relu(bn(h1)@qW2^T+b2) @ W3^T)
    mma_gemm2<<<dim3(H_DIM / 128, B_ROWS / 128), 256, G2SMEM>>>(
        ahip, alop, b2hip, b2lop, b2fp, W3, H_DIM);

    // out = b3 + sum of 8 partial slices
    reduce_out<<<(B_ROWS * D_OUT + 255) / 256, 256>>>(b3, out);

    write_diff<<<1, 1>>>(out, out_size);
}

// round 15
// speedup vs baseline: 1.0592x; 1.0592x over previous
#include <cuda_runtime.h>
#include <cuda_bf16.h>
#include <cstdint>
#include <math.h>

// Problem dims (fixed by the dataset)
#define B_ROWS 65536
#define D_IN   784
#define H_DIM  512
#define D_OUT  10
#define KCODE  512
#define BN_EPS 1e-5f

// ---------------- scratch (static device globals; no allocations) ----------------
__device__ __nv_bfloat16 g_b1hi[H_DIM * D_IN];           // split qW1
__device__ __nv_bfloat16 g_b1lo[H_DIM * D_IN];
__device__ float g_qW2[H_DIM * H_DIM];                   // fp32 qW2 (pre-fold)
__device__ __nv_bfloat16 g_b2hi[H_DIM * H_DIM];          // split (qW2 * s)
__device__ __nv_bfloat16 g_b2lo[H_DIM * H_DIM];
__device__ float g_b2f[H_DIM];                           // b2 + qW2 @ t
__device__ float g_h1[(size_t)B_ROWS * H_DIM];
__device__ float g_part[(size_t)8 * B_ROWS * D_OUT];     // out partials
__device__ float g_colsum[H_DIM];
__device__ float g_colsumsq[H_DIM];
__device__ float g_s[H_DIM];
__device__ float g_t[H_DIM];
__device__ float g_diff1;
__device__ float g_diff2;

// ---------------- zero accumulators ----------------
__global__ void zero_accums() {
    int t = threadIdx.x;
    if (t < H_DIM) { g_colsum[t] = 0.f; g_colsumsq[t] = 0.f; }
    if (t == 0) { g_diff1 = 0.f; g_diff2 = 0.f; }
}

// Reference-replicating fp32 helpers (no contraction allowed)
__device__ __forceinline__ float sq_sum_seq(const float* v, int n) {
    float s = __fmul_rn(v[0], v[0]);
    for (int d = 1; d < n; d++) s = __fadd_rn(s, __fmul_rn(v[d], v[d]));
    return s;
}
__device__ __forceinline__ void split_bf16(float x, __nv_bfloat16& h, __nv_bfloat16& l) {
    h = __float2bfloat16_rn(x);
    l = __float2bfloat16_rn(__fsub_rn(x, __bfloat162float(h)));
}
__device__ __forceinline__ uint32_t pack2(__nv_bfloat16 a, __nv_bfloat16 b) {
    __nv_bfloat162 h2 = __halves2bfloat162(a, b);
    return *(uint32_t*)&h2;
}

// ---------------- merged VQ quantize (argmin logic unchanged from passing R3) ----------------
// blocks [0, 448): W1 path (split bf16 out);  blocks [448, 960): W2 path (fp32 qW2 out)
__global__ void quant_all(const float* __restrict__ W1, const float* __restrict__ E1,
                          const float* __restrict__ W2, const float* __restrict__ E2) {
    extern __shared__ float smemq[];
    if (blockIdx.x < 448) {
        float* sE  = smemq;
        float* sSe = smemq + KCODE * 28;

        for (int i = threadIdx.x; i < KCODE * 28; i += 128) {
            int k = i / 28, d = i % 28;
            sE[k * 28 + d] = E1[d * KCODE + k];
        }
        __syncthreads();
        for (int k = threadIdx.x; k < KCODE; k += 128)
            sSe[k] = sq_sum_seq(sE + k * 28, 28);
        __syncthreads();

        int gid = blockIdx.x * 128 + threadIdx.x;
        int blk = gid >> 2;
        int sub = gid & 3;
        int og = blk / 112;
        int ig = blk - og * 112;

        float v[28];
#pragma unroll
        for (int im = 0; im < 7; im++)
#pragma unroll
            for (int om = 0; om < 4; om++)
                v[im * 4 + om] = W1[(og * 4 + om) * D_IN + ig * 7 + im];
        float Sv = sq_sum_seq(v, 28);

        float best = 3.402823e38f;
        int bi = 0x7fffffff;
        for (int i = 0; i < 128; i++) {
            int k = (i << 2) | sub;
            const float* e = sE + k * 28;
            float dot = 0.f;
#pragma unroll
            for (int d = 0; d < 28; d++) dot = __fmaf_rn(v[d], e[d], dot);
            float dist = __fadd_rn(__fsub_rn(Sv, __fmul_rn(2.0f, dot)), sSe[k]);
            if (dist < best) { best = dist; bi = k; }
        }
#pragma unroll
        for (int off = 2; off >= 1; off >>= 1) {
            float ob = __shfl_down_sync(0xffffffffu, best, off);
            int   oi = __shfl_down_sync(0xffffffffu, bi, off);
            if (ob < best || (ob == best && oi < bi)) { best = ob; bi = oi; }
        }
        if (sub == 0) {
            const float* e = sE + bi * 28;
            float dsum = 0.f;
#pragma unroll
            for (int im = 0; im < 7; im++)
#pragma unroll
                for (int om = 0; om < 4; om++) {
                    int d = im * 4 + om;
                    float q = e[d];
                    int idx = (og * 4 + om) * D_IN + ig * 7 + im;
                    __nv_bfloat16 h, l;
                    split_bf16(q, h, l);
                    g_b1hi[idx] = h; g_b1lo[idx] = l;
                    float df = q - v[d];
                    dsum = fmaf(df, df, dsum);
                }
            atomicAdd(&g_diff1, dsum);
        }
    } else {
        float* sE  = smemq;                    // [KCODE][17]
        float* sSe = smemq + KCODE * 17;

        for (int i = threadIdx.x; i < KCODE * 16; i += 128) {
            int k = i >> 4, d = i & 15;
            sE[k * 17 + d] = E2[d * KCODE + k];
        }
        __syncthreads();
        for (int k = threadIdx.x; k < KCODE; k += 128) {
            const float* e = sE + k * 17;
            float s = __fmul_rn(e[0], e[0]);
            for (int d = 1; d < 16; d++) s = __fadd_rn(s, __fmul_rn(e[d], e[d]));
            sSe[k] = s;
        }
        __syncthreads();

        int gid = (blockIdx.x - 448) * 128 + threadIdx.x;
        int blk = gid >> 2;
        int sub = gid & 3;
        int og = blk >> 5;
        int ig = blk & 31;

        float v[16];
        const float4* wp = (const float4*)(W2 + og * H_DIM + ig * 16);
#pragma unroll
        for (int q4 = 0; q4 < 4; q4++) {
            float4 w = wp[q4];
            v[q4 * 4 + 0] = w.x; v[q4 * 4 + 1] = w.y; v[q4 * 4 + 2] = w.z; v[q4 * 4 + 3] = w.w;
        }
        float Sv = sq_sum_seq(v, 16);

        float best = 3.402823e38f;
        int bi = 0x7fffffff;
        for (int i = 0; i < 128; i++) {
            int k = (i << 2) | sub;
            const float* e = sE + k * 17;
            float dot = 0.f;
#pragma unroll
            for (int d = 0; d < 16; d++) dot = __fmaf_rn(v[d], e[d], dot);
            float dist = __fadd_rn(__fsub_rn(Sv, __fmul_rn(2.0f, dot)), sSe[k]);
            if (dist < best) { best = dist; bi = k; }
        }
#pragma unroll
        for (int off = 2; off >= 1; off >>= 1) {
            float ob = __shfl_down_sync(0xffffffffu, best, off);
            int   oi = __shfl_down_sync(0xffffffffu, bi, off);
            if (ob < best || (ob == best && oi < bi)) { best = ob; bi = oi; }
        }
        if (sub == 0) {
            const float* e = sE + bi * 17;
            float dsum = 0.f;
#pragma unroll
            for (int d = 0; d < 16; d++) {
                float q = e[d];
                g_qW2[og * H_DIM + ig * 16 + d] = q;
                float df = q - v[d];
                dsum = fmaf(df, df, dsum);
            }
            atomicAdd(&g_diff2, dsum);
        }
    }
}

// ---------------- bf16x3 GEMM (R13 winner): A fp32 in-kernel split, B pre-split cp.async.cg ----------------
#define TILE_SZ 6144                  // 128 rows * 48B
#define SM_A    0                     // 2 bufs x (hi,lo)
#define SM_B    (2 * 2 * TILE_SZ)     // 24576; 4 stages x (hi,lo)
#define GSMEM   (SM_B + 4 * 2 * TILE_SZ)          // 73728

__device__ __forceinline__ uint32_t smem_u32(const void* p) {
    uint32_t a;
    asm("{ .reg .u64 t; cvta.to.shared.u64 t, %1; cvt.u32.u64 %0, t; }" : "=r"(a) : "l"(p));
    return a;
}
__device__ __forceinline__ void cp_async16_cg(uint32_t dst, const void* src) {
    asm volatile("cp.async.cg.shared.global [%0], [%1], 16;" :: "r"(dst), "l"(src));
}
#define CP_COMMIT() asm volatile("cp.async.commit_group;" ::: "memory")
#define CP_WAIT2()  asm volatile("cp.async.wait_group 2;" ::: "memory")
__device__ __forceinline__ void ldsm_x4(uint32_t* r, uint32_t addr) {
    asm volatile("ldmatrix.sync.aligned.m8n8.x4.shared.b16 {%0,%1,%2,%3}, [%4];"
                 : "=r"(r[0]), "=r"(r[1]), "=r"(r[2]), "=r"(r[3]) : "r"(addr));
}
__device__ __forceinline__ void mma_bf16(float* d, const uint32_t* a, const uint32_t* b) {
    asm volatile(
        "mma.sync.aligned.m16n8k16.row.col.f32.bf16.bf16.f32 "
        "{%0,%1,%2,%3}, {%4,%5,%6,%7}, {%8,%9}, {%0,%1,%2,%3};"
        : "+f"(d[0]), "+f"(d[1]), "+f"(d[2]), "+f"(d[3])
        : "r"(a[0]), "r"(a[1]), "r"(a[2]), "r"(a[3]), "r"(b[0]), "r"(b[1]));
}

template <int COLSTATS, int FUSE_OUT>
__global__ __launch_bounds__(256, 2) void mma_gemm_relu(
    const float* __restrict__ A,
    const __nv_bfloat16* __restrict__ Bhi, const __nv_bfloat16* __restrict__ Blo,
    const float* __restrict__ bias, float* __restrict__ C,
    const float* __restrict__ W3g, int K)
{
    extern __shared__ char sm[];
    char* smA = sm + SM_A;
    const uint32_t smA_u = smem_u32(sm) + SM_A;
    const uint32_t smB_u = smem_u32(sm) + SM_B;

    const int tid = threadIdx.x;
    const int wid = tid >> 5, lane = tid & 31;
    const int bm = blockIdx.y * 128;
    const int bn = blockIdx.x * 128;

    const int row = tid >> 1;
    const int colbase = (tid & 1) * 8;
    const float* Ap = A + (size_t)(bm + row) * K + colbase;
    const __nv_bfloat16* bph = Bhi + (size_t)(bn + row) * K + colbase;
    const __nv_bfloat16* bpl = Blo + (size_t)(bn + row) * K + colbase;
    const uint32_t dsto = (uint32_t)(row * 48 + colbase * 2);

    const int nkt = K / 16;

    auto issue_B = [&](int kt, int stage) {
        uint32_t base = smB_u + stage * (2 * TILE_SZ) + dsto;
        const size_t ko = (size_t)kt * 16;
        cp_async16_cg(base, bph + ko);
        cp_async16_cg(base + TILE_SZ, bpl + ko);
    };

    float4 stA0, stA1;
    auto store_A = [&](int buf) {
        float a[8] = {stA0.x, stA0.y, stA0.z, stA0.w, stA1.x, stA1.y, stA1.z, stA1.w};
        float ah[8], al[8];
#pragma unroll
        for (int j = 0; j < 8; j++) {
            float fh = __bfloat162float(__float2bfloat16_rn(a[j]));
            ah[j] = fh; al[j] = __fsub_rn(a[j], fh);
        }
        char* dst = smA + buf * (2 * TILE_SZ) + dsto;
        *(uint4*)dst = make_uint4(pack2(__float2bfloat16_rn(ah[0]), __float2bfloat16_rn(ah[1])),
                                  pack2(__float2bfloat16_rn(ah[2]), __float2bfloat16_rn(ah[3])),
                                  pack2(__float2bfloat16_rn(ah[4]), __float2bfloat16_rn(ah[5])),
                                  pack2(__float2bfloat16_rn(ah[6]), __float2bfloat16_rn(ah[7])));
        *(uint4*)(dst + TILE_SZ) = make_uint4(pack2(__float2bfloat16_rn(al[0]), __float2bfloat16_rn(al[1])),
                                              pack2(__float2bfloat16_rn(al[2]), __float2bfloat16_rn(al[3])),
                                              pack2(__float2bfloat16_rn(al[4]), __float2bfloat16_rn(al[5])),
                                              pack2(__float2bfloat16_rn(al[6]), __float2bfloat16_rn(al[7])));
    };

    float acc[2][8][4];
#pragma unroll
    for (int mt = 0; mt < 2; mt++)
#pragma unroll
        for (int nt = 0; nt < 8; nt++)
#pragma unroll
            for (int j = 0; j < 4; j++) acc[mt][nt][j] = 0.f;

    const int m0w = (wid & 3) * 32;
    const int n0w = (wid >> 2) * 64;
    const int frow = lane >> 2;
    const int fk2 = (lane & 3) * 2;

    const uint32_t arow = (uint32_t)((lane & 7) + ((lane >> 3) & 1) * 8);
    const uint32_t aseg = (uint32_t)(((lane >> 4) & 1) * 16);
    const uint32_t brow = (uint32_t)(((lane >> 4) & 1) * 8 + (lane & 7));
    const uint32_t bseg = (uint32_t)(((lane >> 3) & 1) * 16);

    // prologue: B stages 0..2 in flight; A(0) stored; A(1) staged in regs
    stA0 = *(const float4*)Ap;  stA1 = *(const float4*)(Ap + 4);
    store_A(0);
    issue_B(0, 0); CP_COMMIT();
    issue_B(1, 1); CP_COMMIT();
    issue_B(2, 2); CP_COMMIT();
    if (nkt > 1) {
        stA0 = *(const float4*)(Ap + 16);  stA1 = *(const float4*)(Ap + 20);
    }

    for (int kt = 0; kt < nkt; kt++) {
        CP_WAIT2();
        __syncthreads();
        if (kt + 3 < nkt) issue_B(kt + 3, (kt + 3) & 3);
        CP_COMMIT();

        const uint32_t tAhi = smA_u + (kt & 1) * (2 * TILE_SZ);
        const uint32_t tAlo = tAhi + TILE_SZ;
        const uint32_t tBhi = smB_u + (kt & 3) * (2 * TILE_SZ);
        const uint32_t tBlo = tBhi + TILE_SZ;

        uint32_t ah[2][4], al[2][4];
#pragma unroll
        for (int mt = 0; mt < 2; mt++) {
            uint32_t ao = (uint32_t)((m0w + mt * 16 + arow) * 48) + aseg;
            ldsm_x4(ah[mt], tAhi + ao);
            ldsm_x4(al[mt], tAlo + ao);
        }
#pragma unroll
        for (int ntp = 0; ntp < 4; ntp++) {
            uint32_t bo = (uint32_t)((n0w + ntp * 16 + brow) * 48) + bseg;
            uint32_t bh[4], bl[4];
            ldsm_x4(bh, tBhi + bo);
            ldsm_x4(bl, tBlo + bo);
#pragma unroll
            for (int h = 0; h < 2; h++) {
                int nt = ntp * 2 + h;
#pragma unroll
                for (int mt = 0; mt < 2; mt++) {
                    mma_bf16(acc[mt][nt], ah[mt], bh + h * 2);
                    mma_bf16(acc[mt][nt], ah[mt], bl + h * 2);
                    mma_bf16(acc[mt][nt], al[mt], bh + h * 2);
                }
            }
        }
        // convert/store A(kt+1), prefetch A(kt+2) — overlaps tensor-pipe drain
        if (kt + 1 < nkt) {
            store_A((kt + 1) & 1);
            if (kt + 2 < nkt) {
                const float* ap = Ap + (size_t)(kt + 2) * 16;
                stA0 = *(const float4*)ap;  stA1 = *(const float4*)(ap + 4);
            }
        }
    }

    if (!FUSE_OUT) {
        // epilogue: bias + relu, float2 stores (+ fused column stats for layer 1)
        float cs[8][2], cs2[8][2];
        if (COLSTATS) {
#pragma unroll
            for (int nt = 0; nt < 8; nt++) { cs[nt][0] = cs[nt][1] = 0.f; cs2[nt][0] = cs2[nt][1] = 0.f; }
        }
#pragma unroll
        for (int mt = 0; mt < 2; mt++) {
            int m = bm + m0w + mt * 16 + frow;
#pragma unroll
            for (int nt = 0; nt < 8; nt++) {
                int n = bn + n0w + nt * 8 + fk2;
                float bx = __ldg(&bias[n]), by = __ldg(&bias[n + 1]);
                float o0 = fmaxf(acc[mt][nt][0] + bx, 0.f);
                float o1 = fmaxf(acc[mt][nt][1] + by, 0.f);
                float o2 = fmaxf(acc[mt][nt][2] + bx, 0.f);
                float o3 = fmaxf(acc[mt][nt][3] + by, 0.f);
                *(float2*)(C + (size_t)m * H_DIM + n) = make_float2(o0, o1);
                *(float2*)(C + (size_t)(m + 8) * H_DIM + n) = make_float2(o2, o3);
                if (COLSTATS) {
                    cs[nt][0] += o0 + o2;   cs[nt][1] += o1 + o3;
                    cs2[nt][0] = fmaf(o0, o0, fmaf(o2, o2, cs2[nt][0]));
                    cs2[nt][1] = fmaf(o1, o1, fmaf(o3, o3, cs2[nt][1]));
                }
            }
        }
        if (COLSTATS) {
#pragma unroll
            for (int off = 4; off <= 16; off <<= 1)
#pragma unroll
                for (int nt = 0; nt < 8; nt++)
#pragma unroll
                    for (int j = 0; j < 2; j++) {
                        cs[nt][j]  += __shfl_down_sync(0xffffffffu, cs[nt][j], off);
                        cs2[nt][j] += __shfl_down_sync(0xffffffffu, cs2[nt][j], off);
                    }
            if (lane < 4) {
#pragma unroll
                for (int nt = 0; nt < 8; nt++)
#pragma unroll
                    for (int j = 0; j < 2; j++) {
                        int n = bn + n0w + nt * 8 + lane * 2 + j;
                        atomicAdd(&g_colsum[n], cs[nt][j]);
                        atomicAdd(&g_colsumsq[n], cs2[nt][j]);
                    }
            }
        }
    } else {
        // fused output layer: partials of relu(acc+bias) @ W3^T into g_part (no atomics)
        __syncthreads();
        float* sW3 = (float*)sm;     // [10][128] W3 slice for this bn
        for (int idx = tid; idx < 10 * 128; idx += 256) {
            int j = idx >> 7, nl = idx & 127;
            sW3[idx] = W3g[j * H_DIM + bn + nl];
        }
        __syncthreads();
        const int half = wid >> 2;
        float* pslice = g_part + ((size_t)(blockIdx.x * 2 + half)) * ((size_t)B_ROWS * D_OUT);
#pragma unroll
        for (int mt = 0; mt < 2; mt++) {
            float p0[10], p1[10];
#pragma unroll
            for (int j = 0; j < 10; j++) { p0[j] = 0.f; p1[j] = 0.f; }
#pragma unroll
            for (int nt = 0; nt < 8; nt++) {
                int nl = n0w + nt * 8 + fk2;
                float bx = __ldg(&bias[bn + nl]), by = __ldg(&bias[bn + nl + 1]);
                float o0 = fmaxf(acc[mt][nt][0] + bx, 0.f);
                float o1 = fmaxf(acc[mt][nt][1] + by, 0.f);
                float o2 = fmaxf(acc[mt][nt][2] + bx, 0.f);
                float o3 = fmaxf(acc[mt][nt][3] + by, 0.f);
#pragma unroll
                for (int j = 0; j < 10; j++) {
                    float w0 = sW3[j * 128 + nl], w1 = sW3[j * 128 + nl + 1];
                    p0[j] = fmaf(o0, w0, fmaf(o1, w1, p0[j]));
                    p1[j] = fmaf(o2, w0, fmaf(o3, w1, p1[j]));
                }
            }
#pragma unroll
            for (int j = 0; j < 10; j++) {
                p0[j] += __shfl_xor_sync(0xffffffffu, p0[j], 1);
                p0[j] += __shfl_xor_sync(0xffffffffu, p0[j], 2);
                p1[j] += __shfl_xor_sync(0xffffffffu, p1[j], 1);
                p1[j] += __shfl_xor_sync(0xffffffffu, p1[j], 2);
            }
            if ((lane & 3) == 0) {
                int m = bm + m0w + mt * 16 + frow;
#pragma unroll
                for (int j = 0; j < 10; j++) {
                    pslice[(size_t)m * D_OUT + j] = p0[j];
                    pslice[(size_t)(m + 8) * D_OUT + j] = p1[j];
                }
            }
        }
    }
}

// ---------------- reduce partials -> out (+ diff scalar) ----------------
__global__ void reduce_out(const float* __restrict__ b3, float* __restrict__ out, int out_size) {
    int i = blockIdx.x * 256 + threadIdx.x;
    if (i < B_ROWS * D_OUT) {
        float s = __ldg(&b3[i % D_OUT]);
#pragma unroll
        for (int p = 0; p < 8; p++)
            s += g_part[(size_t)p * ((size_t)B_ROWS * D_OUT) + i];
        out[i] = s;
    }
    if (i == 0 && out_size > B_ROWS * D_OUT)
        out[out_size - 1] = g_diff1 * (1.f / (float)(H_DIM * D_IN)) +
                            g_diff2 * (1.f / (float)(H_DIM * H_DIM));
}

// ---------------- BN scale/shift ----------------
__global__ void finalize_stats(const float* __restrict__ gamma, const float* __restrict__ beta) {
    int j = threadIdx.x;
    if (j < H_DIM) {
        float mu = g_colsum[j] * (1.f / (float)B_ROWS);
        float var = g_colsumsq[j] * (1.f / (float)B_ROWS) - mu * mu;
        float s = gamma[j] * (1.0f / sqrtf(var + BN_EPS));
        g_s[j] = s;
        g_t[j] = beta[j] - mu * s;
    }
}

// ---------------- fold BN into W2: W2f = qW2 * s (split bf16), b2f = b2 + qW2 @ t ----------------
__global__ void fold_w2(const float* __restrict__ b2) {
    int j = blockIdx.x;
    int t = threadIdx.x;
    __shared__ float red[128];
    float part = 0.f;
    for (int k = t; k < H_DIM; k += 128) {
        float w = g_qW2[j * H_DIM + k];
        float wf = __fmul_rn(w, g_s[k]);
        __nv_bfloat16 h, l;
        split_bf16(wf, h, l);
        g_b2hi[j * H_DIM + k] = h;
        g_b2lo[j * H_DIM + k] = l;
        part = fmaf(w, g_t[k], part);
    }
    red[t] = part;
    __syncthreads();
    for (int off = 64; off; off >>= 1) {
        if (t < off) red[t] += red[t + off];
        __syncthreads();
    }
    if (t == 0) g_b2f[j] = b2[j] + red[0];
}

// ---------------- launcher ----------------
extern "C" void kernel_launch(void* const* d_in, const int* in_sizes, int n_in,
                              void* d_out, int out_size) {
    const float* x      = (const float*)d_in[0];
    const float* W1     = (const float*)d_in[1];
    const float* b1     = (const float*)d_in[2];
    const float* gamma1 = (const float*)d_in[3];
    const float* beta1  = (const float*)d_in[4];
    const float* E1     = (const float*)d_in[5];
    const float* W2     = (const float*)d_in[6];
    const float* b2     = (const float*)d_in[7];
    const float* E2     = (const float*)d_in[8];
    const float* W3     = (const float*)d_in[9];
    const float* b3     = (const float*)d_in[10];
    float* out = (float*)d_out;

    (void)in_sizes; (void)n_in;

    cudaFuncSetAttribute(quant_all, cudaFuncAttributeMaxDynamicSharedMemorySize, 59392);
    cudaFuncSetAttribute((const void*)&mma_gemm_relu<1, 0>, cudaFuncAttributeMaxDynamicSharedMemorySize, GSMEM);
    cudaFuncSetAttribute((const void*)&mma_gemm_relu<0, 1>, cudaFuncAttributeMaxDynamicSharedMemorySize, GSMEM);

    __nv_bfloat16 *b1hip, *b1lop, *b2hip, *b2lop;
    float *h1p, *b2fp;
    cudaGetSymbolAddress((void**)&b1hip, g_b1hi);
    cudaGetSymbolAddress((void**)&b1lop, g_b1lo);
    cudaGetSymbolAddress((void**)&b2hip, g_b2hi);
    cudaGetSymbolAddress((void**)&b2lop, g_b2lo);
    cudaGetSymbolAddress((void**)&h1p, g_h1);
    cudaGetSymbolAddress((void**)&b2fp, g_b2f);

    zero_accums<<<1, 512>>>();
    quant_all<<<960, 128, 59392>>>(W1, E1, W2, E2);

    // h1 = relu(x @ qW1^T + b1)   [R13 mainloop, fused colstats]
    mma_gemm_relu<1, 0><<<dim3(H_DIM / 128, B_ROWS / 128), 256, GSMEM>>>(
        x, b1hip, b1lop, b1, h1p, nullptr, D_IN);

    finalize_stats<<<1, 512>>>(gamma1, beta1);
    fold_w2<<<512, 128>>>(b2);

    // partials of relu(h1 @ (qW2*s)^T + b2f) @ W3^T  (== relu(bn(h1)@qW2^T+b2) @ W3^T)
    mma_gemm_relu<0, 1><<<dim3(H_DIM / 128, B_ROWS / 128), 256, GSMEM>>>(
        h1p, b2hip, b2lop, b2fp, nullptr, W3, H_DIM);

    // out = b3 + sum of 8 partial slices; diff scalar appended
    reduce_out<<<(B_ROWS * D_OUT + 255) / 256, 256>>>(b3, out, out_size);
}